// round 9
// baseline (speedup 1.0000x reference)
#include <cuda_runtime.h>
#include <math.h>
#include <stdint.h>

#define NN 100000
#define NE 1600000
#define NF 133
#define HD 128
#define PADH 132

// ---- scratch (device globals) ----
__device__ float d_g[NN * HD];     // g = dis[n]*(h@W)[n] (fp32)
__device__ float d_h[NN * HD];     // hidden activations between layers
__device__ int   d_cnt[NN];
__device__ int   d_rowptr[NN + 1];
__device__ int   d_head[NN];
__device__ int   d_col[NE];
__device__ float d_dis[NN];

// ---------------- preprocessing ----------------

__global__ void zero_cnt_k() {
    int i = blockIdx.x * blockDim.x + threadIdx.x;
    if (i < NN) d_cnt[i] = 0;
}

__global__ void count_k(const int* __restrict__ ei) {
    int e = blockIdx.x * blockDim.x + threadIdx.x;
    if (e < NE) atomicAdd(&d_cnt[ei[NE + e]], 1);
}

__global__ void scan_k() {
    __shared__ int sums[1024];
    int t = threadIdx.x;
    const int CH = (NN + 1023) / 1024;
    int lo = t * CH;
    int hi = lo + CH; if (hi > NN) hi = NN;
    int s = 0;
    for (int i = lo; i < hi; i++) s += d_cnt[i];
    sums[t] = s;
    __syncthreads();
    for (int off = 1; off < 1024; off <<= 1) {
        int v = 0;
        if (t >= off) v = sums[t - off];
        __syncthreads();
        sums[t] += v;
        __syncthreads();
    }
    int run = sums[t] - s;
    for (int i = lo; i < hi; i++) {
        int c = d_cnt[i];
        d_rowptr[i] = run;
        d_head[i]   = run;
        d_dis[i]    = rsqrtf((float)c + 1.0f);
        run += c;
    }
    if (t == 1023) d_rowptr[NN] = run;
}

__global__ void fill_k(const int* __restrict__ ei) {
    int e = blockIdx.x * blockDim.x + threadIdx.x;
    if (e < NE) {
        int src = ei[e];
        int dst = ei[NE + e];
        int p = atomicAdd(&d_head[dst], 1);
        d_col[p] = src;
    }
}

// ---------------- per-layer GEMM:  g = dis[m] * (H @ W) ----------------
// 128x128 tile, 256 threads, 8x8 outputs/thread as 8x4 f32x2, FFMA2 inner loop.

__global__ __launch_bounds__(256, 2)
void gemm_k(const float* __restrict__ Hext,
            const float* __restrict__ W, int K) {
    __shared__ float hs[32 * PADH];   // [kk][row], transposed, padded
    __shared__ float ws[32 * 128];    // [kk][col]
    const float* H = Hext ? Hext : d_h;

    int tid = threadIdx.x;
    int tx = tid & 15;    // cols tx*8 .. tx*8+7
    int ty = tid >> 4;    // rows ty*8 .. ty*8+7
    int m0 = blockIdx.x * 128;

    uint64_t acc[8][4];
    #pragma unroll
    for (int r = 0; r < 8; r++)
        #pragma unroll
        for (int c = 0; c < 4; c++) acc[r][c] = 0ULL;

    int nkc = (K + 31) / 32;
    for (int kc = 0; kc < nkc; kc++) {
        int k0 = kc * 32;
        #pragma unroll
        for (int i = tid; i < 128 * 32; i += 256) {
            int r = i >> 5, kk = i & 31;
            int gm = m0 + r, gk = k0 + kk;
            hs[kk * PADH + r] = (gm < NN && gk < K) ? H[gm * K + gk] : 0.0f;
        }
        #pragma unroll
        for (int j = tid; j < 32 * 32; j += 256) {
            int kk = j >> 5, c4 = j & 31;
            int gk = k0 + kk;
            float4 v = make_float4(0.f, 0.f, 0.f, 0.f);
            if (gk < K) v = *(const float4*)&W[gk * HD + c4 * 4];
            *(float4*)&ws[kk * 128 + c4 * 4] = v;
        }
        __syncthreads();

        #pragma unroll
        for (int k = 0; k < 32; k++) {
            ulonglong2 wab = *(const ulonglong2*)&ws[k * 128 + tx * 8];
            ulonglong2 wcd = *(const ulonglong2*)&ws[k * 128 + tx * 8 + 4];
            uint64_t wv[4] = {wab.x, wab.y, wcd.x, wcd.y};
            float4 ha = *(const float4*)&hs[k * PADH + ty * 8];
            float4 hb = *(const float4*)&hs[k * PADH + ty * 8 + 4];
            float hv[8] = {ha.x, ha.y, ha.z, ha.w, hb.x, hb.y, hb.z, hb.w};
            uint64_t hp[8];
            #pragma unroll
            for (int r = 0; r < 8; r++)
                asm("mov.b64 %0, {%1, %1};" : "=l"(hp[r]) : "f"(hv[r]));
            #pragma unroll
            for (int r = 0; r < 8; r++)
                #pragma unroll
                for (int c = 0; c < 4; c++)
                    asm("fma.rn.f32x2 %0, %1, %2, %0;"
                        : "+l"(acc[r][c]) : "l"(hp[r]), "l"(wv[c]));
        }
        __syncthreads();
    }

    #pragma unroll
    for (int r = 0; r < 8; r++) {
        int gm = m0 + ty * 8 + r;
        if (gm < NN) {
            float sc = d_dis[gm];
            float o[8];
            #pragma unroll
            for (int c = 0; c < 4; c++) {
                float lo, hi;
                asm("mov.b64 {%0, %1}, %2;" : "=f"(lo), "=f"(hi) : "l"(acc[r][c]));
                o[2 * c]     = lo * sc;
                o[2 * c + 1] = hi * sc;
            }
            float4 o0 = make_float4(o[0], o[1], o[2], o[3]);
            float4 o1 = make_float4(o[4], o[5], o[6], o[7]);
            *(float4*)&d_g[(size_t)gm * HD + tx * 8]     = o0;
            *(float4*)&d_g[(size_t)gm * HD + tx * 8 + 4] = o1;
        }
    }
}

// ---------------- per-layer aggregation + bias + tanh ----------------
// one warp per node; lane owns 16B (4 floats) of the 512B fp32 row.
// Inner loop: SHFL + LDG.128 + 2x add.rn.f32x2 = ~4 issues/edge/lane.

__global__ void agg_k(const float* __restrict__ bias,
                      float* __restrict__ outp) {
    int gw = (blockIdx.x * blockDim.x + threadIdx.x) >> 5;
    int lane = threadIdx.x & 31;
    if (gw >= NN) return;
    float* out = outp ? outp : d_h;

    int n = gw;
    const ulonglong2* grow = (const ulonglong2*)d_g;  // 16B units; 32 per row
    uint64_t a0, a1;
    {   // self term
        ulonglong2 r = grow[(size_t)n * 32 + lane];
        a0 = r.x; a1 = r.y;
    }
    int lo = d_rowptr[n];
    int hi = d_rowptr[n + 1];
    for (int base = lo; base < hi; base += 32) {
        int idx = base + lane;
        int myc = (idx < hi) ? __ldg(&d_col[idx]) : 0;
        int cnt = hi - base; if (cnt > 32) cnt = 32;
        #pragma unroll 4
        for (int j = 0; j < cnt; j++) {
            int s = __shfl_sync(0xffffffffu, myc, j);
            ulonglong2 r = __ldg(&grow[(size_t)s * 32 + lane]);
            asm("add.rn.f32x2 %0, %0, %1;" : "+l"(a0) : "l"(r.x));
            asm("add.rn.f32x2 %0, %0, %1;" : "+l"(a1) : "l"(r.y));
        }
    }
    float sc = d_dis[n];
    float4 b = *(const float4*)&bias[lane * 4];
    float v0, v1, v2, v3;
    asm("mov.b64 {%0, %1}, %2;" : "=f"(v0), "=f"(v1) : "l"(a0));
    asm("mov.b64 {%0, %1}, %2;" : "=f"(v2), "=f"(v3) : "l"(a1));
    float4 o;
    o.x = tanhf(sc * v0 + b.x);
    o.y = tanhf(sc * v1 + b.y);
    o.z = tanhf(sc * v2 + b.z);
    o.w = tanhf(sc * v3 + b.w);
    *(float4*)&out[(size_t)n * HD + lane * 4] = o;
}

// ---------------- launch ----------------

extern "C" void kernel_launch(void* const* d_in, const int* in_sizes, int n_in,
                              void* d_out, int out_size) {
    const float* x  = (const float*)d_in[0];   // [NN, 133]
    const int*   ei = (const int*)d_in[1];     // [2, NE] int32
    const float* W[4] = {(const float*)d_in[2], (const float*)d_in[4],
                         (const float*)d_in[6], (const float*)d_in[8]};
    const float* B[4] = {(const float*)d_in[3], (const float*)d_in[5],
                         (const float*)d_in[7], (const float*)d_in[9]};
    float* out = (float*)d_out;

    zero_cnt_k<<<(NN + 255) / 256, 256>>>();
    count_k<<<(NE + 255) / 256, 256>>>(ei);
    scan_k<<<1, 1024>>>();
    fill_k<<<(NE + 255) / 256, 256>>>(ei);

    const int GEMM_BLOCKS = (NN + 127) / 128;
    const int AGG_BLOCKS  = (NN * 32 + 255) / 256;

    gemm_k<<<GEMM_BLOCKS, 256>>>(x, W[0], NF);
    agg_k<<<AGG_BLOCKS, 256>>>(B[0], nullptr);
    gemm_k<<<GEMM_BLOCKS, 256>>>(nullptr, W[1], HD);
    agg_k<<<AGG_BLOCKS, 256>>>(B[1], nullptr);
    gemm_k<<<GEMM_BLOCKS, 256>>>(nullptr, W[2], HD);
    agg_k<<<AGG_BLOCKS, 256>>>(B[2], nullptr);
    gemm_k<<<GEMM_BLOCKS, 256>>>(nullptr, W[3], HD);
    agg_k<<<AGG_BLOCKS, 256>>>(B[3], out);
}

// round 11
// speedup vs baseline: 1.9644x; 1.9644x over previous
#include <cuda_runtime.h>
#include <cuda_fp16.h>
#include <math.h>
#include <stdint.h>

#define NN 100000
#define NE 1600000
#define NF 133
#define HD 128
#define SA 36    // As row stride (floats): %32==4 -> conflict-free A frag reads
#define SB 136   // Bs row stride (floats): %32==8 -> conflict-free B frag reads

// ---- scratch (device globals) ----
__device__ __half d_gh[NN * HD];   // g = dis[n]*(h@W)[n], fp16 for gather bandwidth
__device__ float d_h[NN * HD];     // hidden activations between layers (fp32)
__device__ int   d_cnt[NN];
__device__ int   d_rowptr[NN + 1];
__device__ int   d_head[NN];
__device__ int   d_col[NE];
__device__ float d_dis[NN];

// ---------------- preprocessing ----------------

__global__ void zero_cnt_k() {
    int i = blockIdx.x * blockDim.x + threadIdx.x;
    if (i < NN) d_cnt[i] = 0;
}

__global__ void count_k(const int* __restrict__ ei) {
    int e = blockIdx.x * blockDim.x + threadIdx.x;
    if (e < NE) atomicAdd(&d_cnt[ei[NE + e]], 1);
}

__global__ void scan_k() {
    __shared__ int sums[1024];
    int t = threadIdx.x;
    const int CH = (NN + 1023) / 1024;
    int lo = t * CH;
    int hi = lo + CH; if (hi > NN) hi = NN;
    int s = 0;
    for (int i = lo; i < hi; i++) s += d_cnt[i];
    sums[t] = s;
    __syncthreads();
    for (int off = 1; off < 1024; off <<= 1) {
        int v = 0;
        if (t >= off) v = sums[t - off];
        __syncthreads();
        sums[t] += v;
        __syncthreads();
    }
    int run = sums[t] - s;
    for (int i = lo; i < hi; i++) {
        int c = d_cnt[i];
        d_rowptr[i] = run;
        d_head[i]   = run;
        d_dis[i]    = rsqrtf((float)c + 1.0f);
        run += c;
    }
    if (t == 1023) d_rowptr[NN] = run;
}

__global__ void fill_k(const int* __restrict__ ei) {
    int e = blockIdx.x * blockDim.x + threadIdx.x;
    if (e < NE) {
        int src = ei[e];
        int dst = ei[NE + e];
        int p = atomicAdd(&d_head[dst], 1);
        d_col[p] = src;
    }
}

// ---------------- per-layer GEMM (tf32 tensor cores) ----------------
// g_fp16 = dis[m] * (H @ W).  Block tile 128x128, 8 warps (4 M x 2 N),
// warp tile 32x64 via mma.sync.m16n8k8.row.col.f32.tf32.tf32.f32.
// tf32 truncation happens once, at smem staging (cvt.rna.tf32.f32).

__device__ __forceinline__ float to_tf32(float x) {
    float y;
    asm("cvt.rna.tf32.f32 %0, %1;" : "=f"(y) : "f"(x));
    return y;
}

__global__ __launch_bounds__(256, 2)
void gemm_k(const float* __restrict__ Hext,
            const float* __restrict__ W, int K) {
    __shared__ float As[128 * SA];  // [row][k], k-chunk of 32
    __shared__ float Bs[32 * SB];   // [k][col]
    const float* H = Hext ? Hext : d_h;

    int tid  = threadIdx.x;
    int wid  = tid >> 5;
    int lane = tid & 31;
    int g    = lane >> 2;   // group id 0..7
    int tig  = lane & 3;    // thread-in-group 0..3
    int wm   = wid & 3;     // warp M index: rows wm*32..+31
    int wn   = wid >> 2;    // warp N index: cols wn*64..+63
    int m0   = blockIdx.x * 128;

    float acc[2][8][4];
    #pragma unroll
    for (int mt = 0; mt < 2; mt++)
        #pragma unroll
        for (int nf = 0; nf < 8; nf++)
            #pragma unroll
            for (int c = 0; c < 4; c++) acc[mt][nf][c] = 0.0f;

    int nkc = (K + 31) / 32;
    for (int kc = 0; kc < nkc; kc++) {
        int k0 = kc * 32;
        // stage A: coalesced scalar loads (handles K=133), tf32 cvt, pad rows
        #pragma unroll
        for (int i = tid; i < 128 * 32; i += 256) {
            int r = i >> 5, kk = i & 31;
            int gm = m0 + r, gk = k0 + kk;
            float v = (gm < NN && gk < K) ? H[(size_t)gm * K + gk] : 0.0f;
            As[r * SA + kk] = to_tf32(v);
        }
        // stage B: coalesced, tf32 cvt
        #pragma unroll
        for (int i = tid; i < 32 * 128; i += 256) {
            int kk = i >> 7, c = i & 127;
            int gk = k0 + kk;
            float v = (gk < K) ? W[gk * HD + c] : 0.0f;
            Bs[kk * SB + c] = to_tf32(v);
        }
        __syncthreads();

        #pragma unroll
        for (int ks = 0; ks < 4; ks++) {
            int kb = ks * 8;
            uint32_t a[2][4];
            #pragma unroll
            for (int mt = 0; mt < 2; mt++) {
                int rb = wm * 32 + mt * 16;
                a[mt][0] = __float_as_uint(As[(rb + g)     * SA + kb + tig]);
                a[mt][1] = __float_as_uint(As[(rb + g + 8) * SA + kb + tig]);
                a[mt][2] = __float_as_uint(As[(rb + g)     * SA + kb + tig + 4]);
                a[mt][3] = __float_as_uint(As[(rb + g + 8) * SA + kb + tig + 4]);
            }
            #pragma unroll
            for (int nf = 0; nf < 8; nf++) {
                int cb = wn * 64 + nf * 8 + g;
                uint32_t b0 = __float_as_uint(Bs[(kb + tig)     * SB + cb]);
                uint32_t b1 = __float_as_uint(Bs[(kb + tig + 4) * SB + cb]);
                #pragma unroll
                for (int mt = 0; mt < 2; mt++) {
                    asm volatile(
                        "mma.sync.aligned.m16n8k8.row.col.f32.tf32.tf32.f32 "
                        "{%0,%1,%2,%3}, {%4,%5,%6,%7}, {%8,%9}, {%0,%1,%2,%3};"
                        : "+f"(acc[mt][nf][0]), "+f"(acc[mt][nf][1]),
                          "+f"(acc[mt][nf][2]), "+f"(acc[mt][nf][3])
                        : "r"(a[mt][0]), "r"(a[mt][1]), "r"(a[mt][2]), "r"(a[mt][3]),
                          "r"(b0), "r"(b1));
                }
            }
        }
        __syncthreads();
    }

    // epilogue: scale by dis[row], convert to fp16, store
    #pragma unroll
    for (int mt = 0; mt < 2; mt++) {
        int r0 = m0 + wm * 32 + mt * 16 + g;
        int r1 = r0 + 8;
        float sc0 = (r0 < NN) ? d_dis[r0] : 0.0f;
        float sc1 = (r1 < NN) ? d_dis[r1] : 0.0f;
        #pragma unroll
        for (int nf = 0; nf < 8; nf++) {
            int col = wn * 64 + nf * 8 + 2 * tig;
            if (r0 < NN) {
                __half2 h = __floats2half2_rn(acc[mt][nf][0] * sc0,
                                              acc[mt][nf][1] * sc0);
                *(__half2*)&d_gh[(size_t)r0 * HD + col] = h;
            }
            if (r1 < NN) {
                __half2 h = __floats2half2_rn(acc[mt][nf][2] * sc1,
                                              acc[mt][nf][3] * sc1);
                *(__half2*)&d_gh[(size_t)r1 * HD + col] = h;
            }
        }
    }
}

// ---------------- per-layer aggregation + bias + tanh (R8 form) ----------------
// one warp per node; lane owns 4 halves (8B) of the 256B fp16 row.

__global__ void agg_k(const float* __restrict__ bias,
                      float* __restrict__ outp) {
    int gw = (blockIdx.x * blockDim.x + threadIdx.x) >> 5;
    int lane = threadIdx.x & 31;
    if (gw >= NN) return;
    float* out = outp ? outp : d_h;

    int n = gw;
    float2 acc[2];
    {   // self term
        uint2 raw = *(const uint2*)&d_gh[(size_t)n * HD + lane * 4];
        const __half2* hp = (const __half2*)&raw;
        acc[0] = __half22float2(hp[0]);
        acc[1] = __half22float2(hp[1]);
    }
    int lo = d_rowptr[n];
    int hi = d_rowptr[n + 1];
    for (int base = lo; base < hi; base += 32) {
        int idx = base + lane;
        int myc = (idx < hi) ? __ldg(&d_col[idx]) : 0;
        int cnt = hi - base; if (cnt > 32) cnt = 32;
        for (int j = 0; j < cnt; j++) {
            int s = __shfl_sync(0xffffffffu, myc, j);
            uint2 raw = __ldg((const uint2*)&d_gh[(size_t)s * HD + lane * 4]);
            const __half2* hp = (const __half2*)&raw;
            float2 v0 = __half22float2(hp[0]);
            float2 v1 = __half22float2(hp[1]);
            acc[0].x += v0.x; acc[0].y += v0.y;
            acc[1].x += v1.x; acc[1].y += v1.y;
        }
    }
    float sc = d_dis[n];
    float4 b = *(const float4*)&bias[lane * 4];
    float4 o;
    o.x = tanhf(sc * acc[0].x + b.x);
    o.y = tanhf(sc * acc[0].y + b.y);
    o.z = tanhf(sc * acc[1].x + b.z);
    o.w = tanhf(sc * acc[1].y + b.w);
    *(float4*)&out[(size_t)n * HD + lane * 4] = o;
}

// ---------------- launch ----------------

extern "C" void kernel_launch(void* const* d_in, const int* in_sizes, int n_in,
                              void* d_out, int out_size) {
    const float* x  = (const float*)d_in[0];   // [NN, 133]
    const int*   ei = (const int*)d_in[1];     // [2, NE] int32
    const float* W[4] = {(const float*)d_in[2], (const float*)d_in[4],
                         (const float*)d_in[6], (const float*)d_in[8]};
    const float* B[4] = {(const float*)d_in[3], (const float*)d_in[5],
                         (const float*)d_in[7], (const float*)d_in[9]};
    float* out = (float*)d_out;

    zero_cnt_k<<<(NN + 255) / 256, 256>>>();
    count_k<<<(NE + 255) / 256, 256>>>(ei);
    scan_k<<<1, 1024>>>();
    fill_k<<<(NE + 255) / 256, 256>>>(ei);

    const int GEMM_BLOCKS = (NN + 127) / 128;
    const int AGG_BLOCKS  = (NN * 32 + 255) / 256;

    gemm_k<<<GEMM_BLOCKS, 256>>>(x, W[0], NF);
    agg_k<<<AGG_BLOCKS, 256>>>(B[0], nullptr);
    gemm_k<<<GEMM_BLOCKS, 256>>>(nullptr, W[1], HD);
    agg_k<<<AGG_BLOCKS, 256>>>(B[1], nullptr);
    gemm_k<<<GEMM_BLOCKS, 256>>>(nullptr, W[2], HD);
    agg_k<<<AGG_BLOCKS, 256>>>(B[2], nullptr);
    gemm_k<<<GEMM_BLOCKS, 256>>>(nullptr, W[3], HD);
    agg_k<<<AGG_BLOCKS, 256>>>(B[3], out);
}

// round 12
// speedup vs baseline: 2.0277x; 1.0322x over previous
#include <cuda_runtime.h>
#include <cuda_fp16.h>
#include <math.h>
#include <stdint.h>

#define NN 100000
#define NE 1600000
#define NF 133
#define HD 128
#define SA 36    // As row stride (floats): %32==4 -> conflict-free A frag reads
#define SB 136   // Bs row stride (floats): %32==8 -> conflict-free B frag reads

// ---- scratch (device globals) ----
__device__ __half d_gh[NN * HD];   // g = dis[n]*(h@W)[n], fp16 for gather bandwidth
__device__ float d_h[NN * HD];     // hidden activations between layers (fp32)
__device__ int   d_cnt[NN];
__device__ int   d_rowptr[NN + 1];
__device__ int   d_head[NN];
__device__ int   d_col[NE];
__device__ float d_dis[NN];

// ---------------- preprocessing ----------------

__global__ void zero_cnt_k() {
    int i = blockIdx.x * blockDim.x + threadIdx.x;
    if (i < NN) d_cnt[i] = 0;
}

__global__ void count_k(const int* __restrict__ ei) {
    int e = blockIdx.x * blockDim.x + threadIdx.x;
    if (e < NE) atomicAdd(&d_cnt[ei[NE + e]], 1);
}

__global__ void scan_k() {
    __shared__ int sums[1024];
    int t = threadIdx.x;
    const int CH = (NN + 1023) / 1024;
    int lo = t * CH;
    int hi = lo + CH; if (hi > NN) hi = NN;
    int s = 0;
    for (int i = lo; i < hi; i++) s += d_cnt[i];
    sums[t] = s;
    __syncthreads();
    for (int off = 1; off < 1024; off <<= 1) {
        int v = 0;
        if (t >= off) v = sums[t - off];
        __syncthreads();
        sums[t] += v;
        __syncthreads();
    }
    int run = sums[t] - s;
    for (int i = lo; i < hi; i++) {
        int c = d_cnt[i];
        d_rowptr[i] = run;
        d_head[i]   = run;
        d_dis[i]    = rsqrtf((float)c + 1.0f);
        run += c;
    }
    if (t == 1023) d_rowptr[NN] = run;
}

__global__ void fill_k(const int* __restrict__ ei) {
    int e = blockIdx.x * blockDim.x + threadIdx.x;
    if (e < NE) {
        int src = ei[e];
        int dst = ei[NE + e];
        int p = atomicAdd(&d_head[dst], 1);
        d_col[p] = src;
    }
}

// ---------------- per-layer GEMM (tf32 tensor cores) ----------------
// g_fp16 = dis[m] * (H @ W).  Block tile 128x128, 8 warps (4 M x 2 N),
// warp tile 32x64 via mma.sync.m16n8k8.row.col.f32.tf32.tf32.f32.

__device__ __forceinline__ float to_tf32(float x) {
    float y;
    asm("cvt.rna.tf32.f32 %0, %1;" : "=f"(y) : "f"(x));
    return y;
}

__global__ __launch_bounds__(256, 2)
void gemm_k(const float* __restrict__ Hext,
            const float* __restrict__ W, int K) {
    __shared__ float As[128 * SA];  // [row][k], k-chunk of 32
    __shared__ float Bs[32 * SB];   // [k][col]
    const float* H = Hext ? Hext : d_h;

    int tid  = threadIdx.x;
    int wid  = tid >> 5;
    int lane = tid & 31;
    int g    = lane >> 2;
    int tig  = lane & 3;
    int wm   = wid & 3;
    int wn   = wid >> 2;
    int m0   = blockIdx.x * 128;

    float acc[2][8][4];
    #pragma unroll
    for (int mt = 0; mt < 2; mt++)
        #pragma unroll
        for (int nf = 0; nf < 8; nf++)
            #pragma unroll
            for (int c = 0; c < 4; c++) acc[mt][nf][c] = 0.0f;

    int nkc = (K + 31) / 32;
    for (int kc = 0; kc < nkc; kc++) {
        int k0 = kc * 32;
        #pragma unroll
        for (int i = tid; i < 128 * 32; i += 256) {
            int r = i >> 5, kk = i & 31;
            int gm = m0 + r, gk = k0 + kk;
            float v = (gm < NN && gk < K) ? H[(size_t)gm * K + gk] : 0.0f;
            As[r * SA + kk] = to_tf32(v);
        }
        #pragma unroll
        for (int i = tid; i < 32 * 128; i += 256) {
            int kk = i >> 7, c = i & 127;
            int gk = k0 + kk;
            float v = (gk < K) ? W[gk * HD + c] : 0.0f;
            Bs[kk * SB + c] = to_tf32(v);
        }
        __syncthreads();

        #pragma unroll
        for (int ks = 0; ks < 4; ks++) {
            int kb = ks * 8;
            uint32_t a[2][4];
            #pragma unroll
            for (int mt = 0; mt < 2; mt++) {
                int rb = wm * 32 + mt * 16;
                a[mt][0] = __float_as_uint(As[(rb + g)     * SA + kb + tig]);
                a[mt][1] = __float_as_uint(As[(rb + g + 8) * SA + kb + tig]);
                a[mt][2] = __float_as_uint(As[(rb + g)     * SA + kb + tig + 4]);
                a[mt][3] = __float_as_uint(As[(rb + g + 8) * SA + kb + tig + 4]);
            }
            #pragma unroll
            for (int nf = 0; nf < 8; nf++) {
                int cb = wn * 64 + nf * 8 + g;
                uint32_t b0 = __float_as_uint(Bs[(kb + tig)     * SB + cb]);
                uint32_t b1 = __float_as_uint(Bs[(kb + tig + 4) * SB + cb]);
                #pragma unroll
                for (int mt = 0; mt < 2; mt++) {
                    asm volatile(
                        "mma.sync.aligned.m16n8k8.row.col.f32.tf32.tf32.f32 "
                        "{%0,%1,%2,%3}, {%4,%5,%6,%7}, {%8,%9}, {%0,%1,%2,%3};"
                        : "+f"(acc[mt][nf][0]), "+f"(acc[mt][nf][1]),
                          "+f"(acc[mt][nf][2]), "+f"(acc[mt][nf][3])
                        : "r"(a[mt][0]), "r"(a[mt][1]), "r"(a[mt][2]), "r"(a[mt][3]),
                          "r"(b0), "r"(b1));
                }
            }
        }
        __syncthreads();
    }

    #pragma unroll
    for (int mt = 0; mt < 2; mt++) {
        int r0 = m0 + wm * 32 + mt * 16 + g;
        int r1 = r0 + 8;
        float sc0 = (r0 < NN) ? d_dis[r0] : 0.0f;
        float sc1 = (r1 < NN) ? d_dis[r1] : 0.0f;
        #pragma unroll
        for (int nf = 0; nf < 8; nf++) {
            int col = wn * 64 + nf * 8 + 2 * tig;
            if (r0 < NN) {
                __half2 h = __floats2half2_rn(acc[mt][nf][0] * sc0,
                                              acc[mt][nf][1] * sc0);
                *(__half2*)&d_gh[(size_t)r0 * HD + col] = h;
            }
            if (r1 < NN) {
                __half2 h = __floats2half2_rn(acc[mt][nf][2] * sc1,
                                              acc[mt][nf][3] * sc1);
                *(__half2*)&d_gh[(size_t)r1 * HD + col] = h;
            }
        }
    }
}

// ---------------- per-layer aggregation + bias + tanh ----------------
// one warp per node; lane owns 4 halves (8B) of the 256B fp16 row.
// 4-way manually batched gathers: 4 independent LDG.64 in flight before
// any accumulate (MLP>=4), loop overhead amortized, fp32 adds in the
// SAME j-order as before (bit-identical rounding).

__global__ void agg_k(const float* __restrict__ bias,
                      float* __restrict__ outp) {
    int gw = (blockIdx.x * blockDim.x + threadIdx.x) >> 5;
    int lane = threadIdx.x & 31;
    if (gw >= NN) return;
    float* out = outp ? outp : d_h;

    const uint2* gh = (const uint2*)d_gh;   // 8B units, 32 per row
    int n = gw;
    float2 acc0, acc1;
    {   // self term
        uint2 raw = gh[(size_t)n * 32 + lane];
        acc0 = __half22float2(*(const __half2*)&raw.x);
        acc1 = __half22float2(*(const __half2*)&raw.y);
    }
    int lo = d_rowptr[n];
    int hi = d_rowptr[n + 1];
    for (int base = lo; base < hi; base += 32) {
        int idx = base + lane;
        int myc = (idx < hi) ? __ldg(&d_col[idx]) : 0;
        int cnt = hi - base; if (cnt > 32) cnt = 32;
        int j = 0;
        for (; j + 4 <= cnt; j += 4) {
            int s0 = __shfl_sync(0xffffffffu, myc, j);
            int s1 = __shfl_sync(0xffffffffu, myc, j + 1);
            int s2 = __shfl_sync(0xffffffffu, myc, j + 2);
            int s3 = __shfl_sync(0xffffffffu, myc, j + 3);
            uint2 r0 = __ldg(&gh[(size_t)s0 * 32 + lane]);
            uint2 r1 = __ldg(&gh[(size_t)s1 * 32 + lane]);
            uint2 r2 = __ldg(&gh[(size_t)s2 * 32 + lane]);
            uint2 r3 = __ldg(&gh[(size_t)s3 * 32 + lane]);
            float2 v;
            v = __half22float2(*(const __half2*)&r0.x); acc0.x += v.x; acc0.y += v.y;
            v = __half22float2(*(const __half2*)&r0.y); acc1.x += v.x; acc1.y += v.y;
            v = __half22float2(*(const __half2*)&r1.x); acc0.x += v.x; acc0.y += v.y;
            v = __half22float2(*(const __half2*)&r1.y); acc1.x += v.x; acc1.y += v.y;
            v = __half22float2(*(const __half2*)&r2.x); acc0.x += v.x; acc0.y += v.y;
            v = __half22float2(*(const __half2*)&r2.y); acc1.x += v.x; acc1.y += v.y;
            v = __half22float2(*(const __half2*)&r3.x); acc0.x += v.x; acc0.y += v.y;
            v = __half22float2(*(const __half2*)&r3.y); acc1.x += v.x; acc1.y += v.y;
        }
        for (; j < cnt; j++) {
            int s = __shfl_sync(0xffffffffu, myc, j);
            uint2 r = __ldg(&gh[(size_t)s * 32 + lane]);
            float2 v;
            v = __half22float2(*(const __half2*)&r.x); acc0.x += v.x; acc0.y += v.y;
            v = __half22float2(*(const __half2*)&r.y); acc1.x += v.x; acc1.y += v.y;
        }
    }
    float sc = d_dis[n];
    float4 b = *(const float4*)&bias[lane * 4];
    float4 o;
    o.x = tanhf(sc * acc0.x + b.x);
    o.y = tanhf(sc * acc0.y + b.y);
    o.z = tanhf(sc * acc1.x + b.z);
    o.w = tanhf(sc * acc1.y + b.w);
    *(float4*)&out[(size_t)n * HD + lane * 4] = o;
}

// ---------------- launch ----------------

extern "C" void kernel_launch(void* const* d_in, const int* in_sizes, int n_in,
                              void* d_out, int out_size) {
    const float* x  = (const float*)d_in[0];   // [NN, 133]
    const int*   ei = (const int*)d_in[1];     // [2, NE] int32
    const float* W[4] = {(const float*)d_in[2], (const float*)d_in[4],
                         (const float*)d_in[6], (const float*)d_in[8]};
    const float* B[4] = {(const float*)d_in[3], (const float*)d_in[5],
                         (const float*)d_in[7], (const float*)d_in[9]};
    float* out = (float*)d_out;

    zero_cnt_k<<<(NN + 255) / 256, 256>>>();
    count_k<<<(NE + 255) / 256, 256>>>(ei);
    scan_k<<<1, 1024>>>();
    fill_k<<<(NE + 255) / 256, 256>>>(ei);

    const int GEMM_BLOCKS = (NN + 127) / 128;
    const int AGG_BLOCKS  = (NN * 32 + 255) / 256;

    gemm_k<<<GEMM_BLOCKS, 256>>>(x, W[0], NF);
    agg_k<<<AGG_BLOCKS, 256>>>(B[0], nullptr);
    gemm_k<<<GEMM_BLOCKS, 256>>>(nullptr, W[1], HD);
    agg_k<<<AGG_BLOCKS, 256>>>(B[1], nullptr);
    gemm_k<<<GEMM_BLOCKS, 256>>>(nullptr, W[2], HD);
    agg_k<<<AGG_BLOCKS, 256>>>(B[2], nullptr);
    gemm_k<<<GEMM_BLOCKS, 256>>>(nullptr, W[3], HD);
    agg_k<<<AGG_BLOCKS, 256>>>(B[3], out);
}